// round 5
// baseline (speedup 1.0000x reference)
#include <cuda_runtime.h>

#define NN 50000
#define EE 800000
#define DD 128
#define LL 3

// ---------------- scratch (device globals: no allocation allowed) ----------------
__device__ int    g_deg[NN];
__device__ int    g_off[NN + 1];
__device__ int    g_cur[NN];
__device__ int    g_eid[EE];
__device__ __align__(16) float  g_Hagg[(size_t)NN * DD];
__device__ __align__(16) float  g_H1[(size_t)NN * DD];
__device__ __align__(16) float  g_H2[(size_t)NN * DD];
__device__ double g_bn[4 * DD];           // sum1, sumsq1, sum2, sumsq2
__device__ __align__(16) float  g_sc1[DD];
__device__ __align__(16) float  g_sh1[DD];   // inner BN scale/shift
__device__ __align__(16) float  g_scA[DD];
__device__ __align__(16) float  g_shA[DD];   // outer BN scale/shift

// ---------------- CSR build ----------------
__global__ void hist_k(const int* __restrict__ dst, int* __restrict__ deg) {
    int i = blockIdx.x * blockDim.x + threadIdx.x;
    int st = gridDim.x * blockDim.x;
    for (int e = i; e < EE; e += st) atomicAdd(&deg[dst[e]], 1);
}

__global__ void scan_k(const int* __restrict__ deg, int* __restrict__ off) {
    __shared__ int part[1024];
    int t = threadIdx.x;
    const int CH = (NN + 1023) / 1024;
    int s = t * CH;
    int e = min(s + CH, NN);
    int acc = 0;
    for (int i = s; i < e; i++) acc += deg[i];
    part[t] = acc;
    __syncthreads();
    for (int d = 1; d < 1024; d <<= 1) {
        int v = (t >= d) ? part[t - d] : 0;
        __syncthreads();
        part[t] += v;
        __syncthreads();
    }
    int run = (t == 0) ? 0 : part[t - 1];
    for (int i = s; i < e; i++) { off[i] = run; run += deg[i]; }
    if (t == 1023) off[NN] = part[1023];
}

__global__ void scat_k(const int* __restrict__ dst, int* __restrict__ cur,
                       int* __restrict__ eid) {
    int i = blockIdx.x * blockDim.x + threadIdx.x;
    int st = gridDim.x * blockDim.x;
    for (int e = i; e < EE; e += st) {
        int p = atomicAdd(&cur[dst[e]], 1);
        eid[p] = e;
    }
}

__global__ void init_sc_k(float* sc, float* sh) {
    int d = threadIdx.x;
    sc[d] = 1.0f;
    sh[d] = 0.0f;
}

// ---------------- aggregation: h = x_eff + sum_e relu(x_eff[src] + ea) ----------------
// warp-per-node, float4 per lane. x_eff = (relu_in ? relu : id)(X*sc + sh) fuses the
// previous layer's outer BN (+ReLU) into the read path.
__global__ void __launch_bounds__(256) agg_k(
    const float* __restrict__ X, const float* __restrict__ sc,
    const float* __restrict__ sh, int relu_in,
    const int* __restrict__ src, const float* __restrict__ ea,
    const int* __restrict__ off, const int* __restrict__ eid,
    float* __restrict__ out) {
    int warp = (blockIdx.x * blockDim.x + threadIdx.x) >> 5;
    if (warp >= NN) return;
    int lane = threadIdx.x & 31;
    int d0 = lane * 4;
    int row = warp;

    float4 s4 = *(const float4*)&sc[d0];
    float4 b4 = *(const float4*)&sh[d0];

    float4 v = *(const float4*)&X[(size_t)row * DD + d0];
    float4 acc;
    acc.x = v.x * s4.x + b4.x;
    acc.y = v.y * s4.y + b4.y;
    acc.z = v.z * s4.z + b4.z;
    acc.w = v.w * s4.w + b4.w;
    if (relu_in) {
        acc.x = fmaxf(acc.x, 0.0f); acc.y = fmaxf(acc.y, 0.0f);
        acc.z = fmaxf(acc.z, 0.0f); acc.w = fmaxf(acc.w, 0.0f);
    }

    int i0 = off[row], i1 = off[row + 1];
    int i = i0;
    // 2-edge unroll for MLP on the eid -> src -> X dependent chain
    for (; i + 1 < i1; i += 2) {
        int ea0 = eid[i], ea1 = eid[i + 1];
        int s0 = src[ea0], s1 = src[ea1];
        float4 x0 = *(const float4*)&X[(size_t)s0 * DD + d0];
        float4 x1 = *(const float4*)&X[(size_t)s1 * DD + d0];
        float4 e0 = *(const float4*)&ea[(size_t)ea0 * DD + d0];
        float4 e1 = *(const float4*)&ea[(size_t)ea1 * DD + d0];
        float4 t0, t1;
        t0.x = x0.x * s4.x + b4.x; t0.y = x0.y * s4.y + b4.y;
        t0.z = x0.z * s4.z + b4.z; t0.w = x0.w * s4.w + b4.w;
        t1.x = x1.x * s4.x + b4.x; t1.y = x1.y * s4.y + b4.y;
        t1.z = x1.z * s4.z + b4.z; t1.w = x1.w * s4.w + b4.w;
        if (relu_in) {
            t0.x = fmaxf(t0.x, 0.f); t0.y = fmaxf(t0.y, 0.f);
            t0.z = fmaxf(t0.z, 0.f); t0.w = fmaxf(t0.w, 0.f);
            t1.x = fmaxf(t1.x, 0.f); t1.y = fmaxf(t1.y, 0.f);
            t1.z = fmaxf(t1.z, 0.f); t1.w = fmaxf(t1.w, 0.f);
        }
        acc.x += fmaxf(t0.x + e0.x, 0.f) + fmaxf(t1.x + e1.x, 0.f);
        acc.y += fmaxf(t0.y + e0.y, 0.f) + fmaxf(t1.y + e1.y, 0.f);
        acc.z += fmaxf(t0.z + e0.z, 0.f) + fmaxf(t1.z + e1.z, 0.f);
        acc.w += fmaxf(t0.w + e0.w, 0.f) + fmaxf(t1.w + e1.w, 0.f);
    }
    if (i < i1) {
        int e0i = eid[i];
        int s0 = src[e0i];
        float4 x0 = *(const float4*)&X[(size_t)s0 * DD + d0];
        float4 e0 = *(const float4*)&ea[(size_t)e0i * DD + d0];
        float4 t0;
        t0.x = x0.x * s4.x + b4.x; t0.y = x0.y * s4.y + b4.y;
        t0.z = x0.z * s4.z + b4.z; t0.w = x0.w * s4.w + b4.w;
        if (relu_in) {
            t0.x = fmaxf(t0.x, 0.f); t0.y = fmaxf(t0.y, 0.f);
            t0.z = fmaxf(t0.z, 0.f); t0.w = fmaxf(t0.w, 0.f);
        }
        acc.x += fmaxf(t0.x + e0.x, 0.f);
        acc.y += fmaxf(t0.y + e0.y, 0.f);
        acc.z += fmaxf(t0.z + e0.z, 0.f);
        acc.w += fmaxf(t0.w + e0.w, 0.f);
    }
    *(float4*)&out[(size_t)row * DD + d0] = acc;
}

// ---------------- GEMM: out = f(A) @ W + bias, fused BN-stats epilogue ----------------
// FUSE=1: f(a) = relu(a*insc[k] + insh[k])  (inner BN + ReLU applied on A-tile load)
template <int FUSE>
__global__ void __launch_bounds__(256) gemm_k(
    const float* __restrict__ A, const float* __restrict__ W,
    const float* __restrict__ bias, const float* __restrict__ insc,
    const float* __restrict__ insh, float* __restrict__ out,
    double* __restrict__ csum, double* __restrict__ csq, int M) {
    __shared__ float As[16 * 132];   // k-major, padded
    __shared__ float Bs[16 * 128];
    __shared__ float bb[128], fsc[128], fsh[128];
    __shared__ float cs[128], cq[128];

    int tid = threadIdx.x;
    if (tid < 128) {
        bb[tid] = bias[tid];
        cs[tid] = 0.0f;
        cq[tid] = 0.0f;
        if (FUSE) { fsc[tid] = insc[tid]; fsh[tid] = insh[tid]; }
    }
    int m0 = blockIdx.x * 128;
    int tm = (tid >> 4) * 8;
    int tn = (tid & 15) * 8;
    float acc[8][8];
#pragma unroll
    for (int i = 0; i < 8; i++)
#pragma unroll
        for (int j = 0; j < 8; j++) acc[i][j] = 0.0f;

    for (int kt = 0; kt < 128; kt += 16) {
        __syncthreads();
        // A tile: 128 rows x 16 k, transposed into As[k][m]
#pragma unroll
        for (int i = tid; i < 512; i += 256) {
            int r = i >> 2;
            int c4 = (i & 3) << 2;
            int m = m0 + r;
            float4 v = make_float4(0.f, 0.f, 0.f, 0.f);
            if (m < M) v = *(const float4*)&A[(size_t)m * DD + kt + c4];
            if (FUSE) {
                v.x = fmaxf(v.x * fsc[kt + c4 + 0] + fsh[kt + c4 + 0], 0.0f);
                v.y = fmaxf(v.y * fsc[kt + c4 + 1] + fsh[kt + c4 + 1], 0.0f);
                v.z = fmaxf(v.z * fsc[kt + c4 + 2] + fsh[kt + c4 + 2], 0.0f);
                v.w = fmaxf(v.w * fsc[kt + c4 + 3] + fsh[kt + c4 + 3], 0.0f);
            }
            As[(c4 + 0) * 132 + r] = v.x;
            As[(c4 + 1) * 132 + r] = v.y;
            As[(c4 + 2) * 132 + r] = v.z;
            As[(c4 + 3) * 132 + r] = v.w;
        }
        // W tile: 16 x 128
#pragma unroll
        for (int i = tid; i < 512; i += 256) {
            int r = i >> 5;
            int c4 = (i & 31) << 2;
            *(float4*)&Bs[r * 128 + c4] = *(const float4*)&W[(size_t)(kt + r) * DD + c4];
        }
        __syncthreads();
#pragma unroll
        for (int k = 0; k < 16; k++) {
            float a[8], b[8];
            *(float4*)&a[0] = *(float4*)&As[k * 132 + tm];
            *(float4*)&a[4] = *(float4*)&As[k * 132 + tm + 4];
            *(float4*)&b[0] = *(float4*)&Bs[k * 128 + tn];
            *(float4*)&b[4] = *(float4*)&Bs[k * 128 + tn + 4];
#pragma unroll
            for (int ii = 0; ii < 8; ii++)
#pragma unroll
                for (int jj = 0; jj < 8; jj++)
                    acc[ii][jj] = fmaf(a[ii], b[jj], acc[ii][jj]);
        }
    }
    __syncthreads();

    float colS[8], colQ[8];
#pragma unroll
    for (int j = 0; j < 8; j++) { colS[j] = 0.0f; colQ[j] = 0.0f; }
#pragma unroll
    for (int ii = 0; ii < 8; ii++) {
        int m = m0 + tm + ii;
        if (m < M) {
            float v[8];
#pragma unroll
            for (int j = 0; j < 8; j++) {
                v[j] = acc[ii][j] + bb[tn + j];
                colS[j] += v[j];
                colQ[j] += v[j] * v[j];
            }
            *(float4*)&out[(size_t)m * DD + tn]     = make_float4(v[0], v[1], v[2], v[3]);
            *(float4*)&out[(size_t)m * DD + tn + 4] = make_float4(v[4], v[5], v[6], v[7]);
        }
    }
#pragma unroll
    for (int j = 0; j < 8; j++) {
        atomicAdd(&cs[tn + j], colS[j]);
        atomicAdd(&cq[tn + j], colQ[j]);
    }
    __syncthreads();
    if (tid < 128) {
        atomicAdd(&csum[tid], (double)cs[tid]);
        atomicAdd(&csq[tid], (double)cq[tid]);
    }
}

// ---------------- BN stats -> scale/shift ----------------
__global__ void bnstat_k(const double* __restrict__ sum, const double* __restrict__ sq,
                         const float* __restrict__ gm, const float* __restrict__ bt,
                         float* __restrict__ sc, float* __restrict__ sh) {
    int d = threadIdx.x;
    double m = sum[d] / (double)NN;
    double v = sq[d] / (double)NN - m * m;
    float s = gm[d] * rsqrtf((float)v + 1e-5f);
    sc[d] = s;
    sh[d] = bt[d] - (float)m * s;
}

// ---------------- final BN apply (no relu) to d_out ----------------
__global__ void apply_k(const float* __restrict__ H, const float* __restrict__ sc,
                        const float* __restrict__ sh, float* __restrict__ out) {
    int i = blockIdx.x * blockDim.x + threadIdx.x;
    int total = NN * DD / 4;
    if (i < total) {
        float4 h = ((const float4*)H)[i];
        int d = (i * 4) & (DD - 1);
        float4 o;
        o.x = h.x * sc[d + 0] + sh[d + 0];
        o.y = h.y * sc[d + 1] + sh[d + 1];
        o.z = h.z * sc[d + 2] + sh[d + 2];
        o.w = h.w * sc[d + 3] + sh[d + 3];
        ((float4*)out)[i] = o;
    }
}

// ---------------- launch ----------------
extern "C" void kernel_launch(void* const* d_in, const int* in_sizes, int n_in,
                              void* d_out, int out_size) {
    const float* x   = (const float*)d_in[0];
    const int*   ei  = (const int*)d_in[1];     // int32 (JAX default config downcasts int64)
    const float* ea  = (const float*)d_in[2];
    const float* W1  = (const float*)d_in[4];
    const float* b1  = (const float*)d_in[5];
    const float* gmm = (const float*)d_in[6];
    const float* bmm = (const float*)d_in[7];
    const float* W2  = (const float*)d_in[8];
    const float* b2  = (const float*)d_in[9];
    const float* go  = (const float*)d_in[10];
    const float* bo  = (const float*)d_in[11];
    float*       out = (float*)d_out;

    const int* src = ei;
    const int* dst = ei + EE;

    int *deg, *off, *cur, *eid;
    float *Hagg, *H1, *H2, *sc1, *sh1, *scA, *shA;
    double* bn;
    cudaGetSymbolAddress((void**)&deg, g_deg);
    cudaGetSymbolAddress((void**)&off, g_off);
    cudaGetSymbolAddress((void**)&cur, g_cur);
    cudaGetSymbolAddress((void**)&eid, g_eid);
    cudaGetSymbolAddress((void**)&Hagg, g_Hagg);
    cudaGetSymbolAddress((void**)&H1, g_H1);
    cudaGetSymbolAddress((void**)&H2, g_H2);
    cudaGetSymbolAddress((void**)&bn, g_bn);
    cudaGetSymbolAddress((void**)&sc1, g_sc1);
    cudaGetSymbolAddress((void**)&sh1, g_sh1);
    cudaGetSymbolAddress((void**)&scA, g_scA);
    cudaGetSymbolAddress((void**)&shA, g_shA);

    // CSR build (once per launch, reused by all 3 layers)
    cudaMemsetAsync(deg, 0, NN * sizeof(int), 0);
    hist_k<<<1024, 256>>>(dst, deg);
    scan_k<<<1, 1024>>>(deg, off);
    cudaMemcpyAsync(cur, off, NN * sizeof(int), cudaMemcpyDeviceToDevice, 0);
    scat_k<<<1024, 256>>>(dst, cur, eid);
    init_sc_k<<<1, 128>>>(scA, shA);

    int MB = (NN + 127) / 128;
    int AGG_BLOCKS = (NN * 32 + 255) / 256;   // warp per node, 8 nodes/block
    for (int i = 0; i < LL; i++) {
        cudaMemsetAsync(bn, 0, 4 * DD * sizeof(double), 0);
        const float* Xin = (i == 0) ? x : H2;
        agg_k<<<AGG_BLOCKS, 256>>>(Xin, scA, shA, (i > 0) ? 1 : 0, src, ea, off, eid, Hagg);
        gemm_k<0><<<MB, 256>>>(Hagg, W1 + (size_t)i * DD * DD, b1 + i * DD,
                               nullptr, nullptr, H1, bn, bn + DD, NN);
        bnstat_k<<<1, 128>>>(bn, bn + DD, gmm + i * DD, bmm + i * DD, sc1, sh1);
        gemm_k<1><<<MB, 256>>>(H1, W2 + (size_t)i * DD * DD, b2 + i * DD,
                               sc1, sh1, H2, bn + 2 * DD, bn + 3 * DD, NN);
        bnstat_k<<<1, 128>>>(bn + 2 * DD, bn + 3 * DD, go + i * DD, bo + i * DD, scA, shA);
    }
    apply_k<<<(NN * DD / 4 + 255) / 256, 256>>>(H2, scA, shA, out);
}

// round 6
// speedup vs baseline: 1.1084x; 1.1084x over previous
#include <cuda_runtime.h>
#include <cstdint>

#define NN 50000
#define EE 800000
#define DD 128
#define LL 3

// ---------------- scratch (device globals: no allocation allowed) ----------------
__device__ int    g_deg[NN];
__device__ int    g_off[NN + 1];
__device__ int    g_cur[NN];
__device__ int    g_eid[EE];
__device__ __align__(16) float  g_Hagg[(size_t)NN * DD];
__device__ __align__(16) float  g_H1[(size_t)NN * DD];
__device__ __align__(16) float  g_H2[(size_t)NN * DD];
__device__ double g_bn[4 * DD];           // sum1, sumsq1, sum2, sumsq2
__device__ __align__(16) float  g_sc1[DD];
__device__ __align__(16) float  g_sh1[DD];   // inner BN scale/shift
__device__ __align__(16) float  g_scA[DD];
__device__ __align__(16) float  g_shA[DD];   // outer BN scale/shift

// ---------------- CSR build ----------------
__global__ void hist_k(const int* __restrict__ dst, int* __restrict__ deg) {
    int i = blockIdx.x * blockDim.x + threadIdx.x;
    int st = gridDim.x * blockDim.x;
    for (int e = i; e < EE; e += st) atomicAdd(&deg[dst[e]], 1);
}

__global__ void scan_k(const int* __restrict__ deg, int* __restrict__ off) {
    __shared__ int part[1024];
    int t = threadIdx.x;
    const int CH = (NN + 1023) / 1024;
    int s = t * CH;
    int e = min(s + CH, NN);
    int acc = 0;
    for (int i = s; i < e; i++) acc += deg[i];
    part[t] = acc;
    __syncthreads();
    for (int d = 1; d < 1024; d <<= 1) {
        int v = (t >= d) ? part[t - d] : 0;
        __syncthreads();
        part[t] += v;
        __syncthreads();
    }
    int run = (t == 0) ? 0 : part[t - 1];
    for (int i = s; i < e; i++) { off[i] = run; run += deg[i]; }
    if (t == 1023) off[NN] = part[1023];
}

__global__ void scat_k(const int* __restrict__ dst, int* __restrict__ cur,
                       int* __restrict__ eid) {
    int i = blockIdx.x * blockDim.x + threadIdx.x;
    int st = gridDim.x * blockDim.x;
    for (int e = i; e < EE; e += st) {
        int p = atomicAdd(&cur[dst[e]], 1);
        eid[p] = e;
    }
}

__global__ void init_sc_k(float* sc, float* sh) {
    int d = threadIdx.x;
    sc[d] = 1.0f;
    sh[d] = 0.0f;
}

// ---------------- aggregation: h = x_eff + sum_e relu(x_eff[src] + ea) ----------------
__global__ void __launch_bounds__(256) agg_k(
    const float* __restrict__ X, const float* __restrict__ sc,
    const float* __restrict__ sh, int relu_in,
    const int* __restrict__ src, const float* __restrict__ ea,
    const int* __restrict__ off, const int* __restrict__ eid,
    float* __restrict__ out) {
    int warp = (blockIdx.x * blockDim.x + threadIdx.x) >> 5;
    if (warp >= NN) return;
    int lane = threadIdx.x & 31;
    int d0 = lane * 4;
    int row = warp;

    float4 s4 = *(const float4*)&sc[d0];
    float4 b4 = *(const float4*)&sh[d0];

    float4 v = *(const float4*)&X[(size_t)row * DD + d0];
    float4 acc;
    acc.x = v.x * s4.x + b4.x;
    acc.y = v.y * s4.y + b4.y;
    acc.z = v.z * s4.z + b4.z;
    acc.w = v.w * s4.w + b4.w;
    if (relu_in) {
        acc.x = fmaxf(acc.x, 0.0f); acc.y = fmaxf(acc.y, 0.0f);
        acc.z = fmaxf(acc.z, 0.0f); acc.w = fmaxf(acc.w, 0.0f);
    }

    int i0 = off[row], i1 = off[row + 1];
    int i = i0;
    for (; i + 1 < i1; i += 2) {
        int ea0 = eid[i], ea1 = eid[i + 1];
        int s0 = src[ea0], s1 = src[ea1];
        float4 x0 = *(const float4*)&X[(size_t)s0 * DD + d0];
        float4 x1 = *(const float4*)&X[(size_t)s1 * DD + d0];
        float4 e0 = *(const float4*)&ea[(size_t)ea0 * DD + d0];
        float4 e1 = *(const float4*)&ea[(size_t)ea1 * DD + d0];
        float4 t0, t1;
        t0.x = x0.x * s4.x + b4.x; t0.y = x0.y * s4.y + b4.y;
        t0.z = x0.z * s4.z + b4.z; t0.w = x0.w * s4.w + b4.w;
        t1.x = x1.x * s4.x + b4.x; t1.y = x1.y * s4.y + b4.y;
        t1.z = x1.z * s4.z + b4.z; t1.w = x1.w * s4.w + b4.w;
        if (relu_in) {
            t0.x = fmaxf(t0.x, 0.f); t0.y = fmaxf(t0.y, 0.f);
            t0.z = fmaxf(t0.z, 0.f); t0.w = fmaxf(t0.w, 0.f);
            t1.x = fmaxf(t1.x, 0.f); t1.y = fmaxf(t1.y, 0.f);
            t1.z = fmaxf(t1.z, 0.f); t1.w = fmaxf(t1.w, 0.f);
        }
        acc.x += fmaxf(t0.x + e0.x, 0.f) + fmaxf(t1.x + e1.x, 0.f);
        acc.y += fmaxf(t0.y + e0.y, 0.f) + fmaxf(t1.y + e1.y, 0.f);
        acc.z += fmaxf(t0.z + e0.z, 0.f) + fmaxf(t1.z + e1.z, 0.f);
        acc.w += fmaxf(t0.w + e0.w, 0.f) + fmaxf(t1.w + e1.w, 0.f);
    }
    if (i < i1) {
        int e0i = eid[i];
        int s0 = src[e0i];
        float4 x0 = *(const float4*)&X[(size_t)s0 * DD + d0];
        float4 e0 = *(const float4*)&ea[(size_t)e0i * DD + d0];
        float4 t0;
        t0.x = x0.x * s4.x + b4.x; t0.y = x0.y * s4.y + b4.y;
        t0.z = x0.z * s4.z + b4.z; t0.w = x0.w * s4.w + b4.w;
        if (relu_in) {
            t0.x = fmaxf(t0.x, 0.f); t0.y = fmaxf(t0.y, 0.f);
            t0.z = fmaxf(t0.z, 0.f); t0.w = fmaxf(t0.w, 0.f);
        }
        acc.x += fmaxf(t0.x + e0.x, 0.f);
        acc.y += fmaxf(t0.y + e0.y, 0.f);
        acc.z += fmaxf(t0.z + e0.z, 0.f);
        acc.w += fmaxf(t0.w + e0.w, 0.f);
    }
    *(float4*)&out[(size_t)row * DD + d0] = acc;
}

// ---------------- tf32 helpers ----------------
__device__ __forceinline__ void tf32split(float a, float& hi, float& lo) {
    uint32_t u;
    asm("cvt.rna.tf32.f32 %0, %1;" : "=r"(u) : "f"(a));
    float h = __uint_as_float(u);
    float d = a - h;
    uint32_t ul;
    asm("cvt.rna.tf32.f32 %0, %1;" : "=r"(ul) : "f"(d));
    hi = h;
    lo = __uint_as_float(ul);
}

#define MMA_TF32(d, a, b)                                                     \
    asm volatile(                                                             \
        "mma.sync.aligned.m16n8k8.row.col.f32.tf32.tf32.f32 "                 \
        "{%0,%1,%2,%3},{%4,%5,%6,%7},{%8,%9},{%0,%1,%2,%3};"                  \
        : "+f"((d)[0]), "+f"((d)[1]), "+f"((d)[2]), "+f"((d)[3])              \
        : "r"((a)[0]), "r"((a)[1]), "r"((a)[2]), "r"((a)[3]),                 \
          "r"((b)[0]), "r"((b)[1]))

#define RED_GID(v)                                    \
    v += __shfl_xor_sync(0xffffffffu, v, 4);          \
    v += __shfl_xor_sync(0xffffffffu, v, 8);          \
    v += __shfl_xor_sync(0xffffffffu, v, 16);

// ---------------- tensor-core GEMM (3xTF32): out = f(A) @ W + bias ----------------
// FUSE=1: f(a) = relu(a*insc[k] + insh[k]); fused BN-stats epilogue (col sums).
// Block: 128(M)x128(N), 8 warps as 4(M)x2(N), warp tile 32x64, K-chunks of 16.
#define ASTR 20    // A smem stride (words): (20*r + k) % 32 conflict-free
#define BSTR 136   // B smem stride (words): (136*k + n) % 32 conflict-free
template <int FUSE>
__global__ void __launch_bounds__(256) gemm_tc(
    const float* __restrict__ A, const float* __restrict__ W,
    const float* __restrict__ bias, const float* __restrict__ insc,
    const float* __restrict__ insh, float* __restrict__ out,
    double* __restrict__ csum, double* __restrict__ csq, int M) {
    __shared__ float AsH[128 * ASTR], AsL[128 * ASTR];
    __shared__ float BsH[16 * BSTR],  BsL[16 * BSTR];
    __shared__ float bb[128], fsc[128], fsh[128];
    __shared__ float cs[128], cq[128];

    int tid = threadIdx.x;
    int lane = tid & 31, wid = tid >> 5;
    int wm = wid >> 1, wn = wid & 1;
    int gid = lane >> 2, tig = lane & 3;
    int m0 = blockIdx.x * 128;

    if (tid < 128) {
        bb[tid] = bias[tid];
        cs[tid] = 0.0f;
        cq[tid] = 0.0f;
        if (FUSE) { fsc[tid] = insc[tid]; fsh[tid] = insh[tid]; }
    }

    float acc[2][8][4];
#pragma unroll
    for (int mt = 0; mt < 2; mt++)
#pragma unroll
        for (int nt = 0; nt < 8; nt++)
#pragma unroll
            for (int r = 0; r < 4; r++) acc[mt][nt][r] = 0.0f;

    for (int ch = 0; ch < 8; ch++) {
        int kc = ch * 16;
        __syncthreads();
        // A tile: 128 rows x 16 k, split to hi/lo
#pragma unroll
        for (int i = tid; i < 512; i += 256) {
            int r = i >> 2;
            int c4 = (i & 3) << 2;
            float4 v = make_float4(0.f, 0.f, 0.f, 0.f);
            if (m0 + r < M) v = *(const float4*)&A[(size_t)(m0 + r) * DD + kc + c4];
            float vv[4] = {v.x, v.y, v.z, v.w};
#pragma unroll
            for (int j = 0; j < 4; j++) {
                float a = vv[j];
                if (FUSE) a = fmaxf(a * fsc[kc + c4 + j] + fsh[kc + c4 + j], 0.0f);
                float h, l;
                tf32split(a, h, l);
                AsH[r * ASTR + c4 + j] = h;
                AsL[r * ASTR + c4 + j] = l;
            }
        }
        // B tile: 16 k x 128 n, split to hi/lo
#pragma unroll
        for (int i = tid; i < 512; i += 256) {
            int r = i >> 5;
            int c4 = (i & 31) << 2;
            float4 w = *(const float4*)&W[(size_t)(kc + r) * DD + c4];
            float vv[4] = {w.x, w.y, w.z, w.w};
#pragma unroll
            for (int j = 0; j < 4; j++) {
                float h, l;
                tf32split(vv[j], h, l);
                BsH[r * BSTR + c4 + j] = h;
                BsL[r * BSTR + c4 + j] = l;
            }
        }
        __syncthreads();
#pragma unroll
        for (int ks = 0; ks < 2; ks++) {
            int k0 = ks * 8;
            uint32_t aH[2][4], aL[2][4], bH[8][2], bL[8][2];
#pragma unroll
            for (int mt = 0; mt < 2; mt++) {
                int r0 = wm * 32 + mt * 16 + gid;
                aH[mt][0] = __float_as_uint(AsH[r0 * ASTR + k0 + tig]);
                aH[mt][1] = __float_as_uint(AsH[(r0 + 8) * ASTR + k0 + tig]);
                aH[mt][2] = __float_as_uint(AsH[r0 * ASTR + k0 + tig + 4]);
                aH[mt][3] = __float_as_uint(AsH[(r0 + 8) * ASTR + k0 + tig + 4]);
                aL[mt][0] = __float_as_uint(AsL[r0 * ASTR + k0 + tig]);
                aL[mt][1] = __float_as_uint(AsL[(r0 + 8) * ASTR + k0 + tig]);
                aL[mt][2] = __float_as_uint(AsL[r0 * ASTR + k0 + tig + 4]);
                aL[mt][3] = __float_as_uint(AsL[(r0 + 8) * ASTR + k0 + tig + 4]);
            }
#pragma unroll
            for (int nt = 0; nt < 8; nt++) {
                int c = wn * 64 + nt * 8 + gid;
                bH[nt][0] = __float_as_uint(BsH[(k0 + tig) * BSTR + c]);
                bH[nt][1] = __float_as_uint(BsH[(k0 + tig + 4) * BSTR + c]);
                bL[nt][0] = __float_as_uint(BsL[(k0 + tig) * BSTR + c]);
                bL[nt][1] = __float_as_uint(BsL[(k0 + tig + 4) * BSTR + c]);
            }
#pragma unroll
            for (int mt = 0; mt < 2; mt++)
#pragma unroll
                for (int nt = 0; nt < 8; nt++) {
                    MMA_TF32(acc[mt][nt], aH[mt], bH[nt]);
                    MMA_TF32(acc[mt][nt], aH[mt], bL[nt]);
                    MMA_TF32(acc[mt][nt], aL[mt], bH[nt]);
                }
        }
    }

    // epilogue: bias add, store, fused column sums (shfl-reduced over gid)
#pragma unroll
    for (int nt = 0; nt < 8; nt++) {
        int c = wn * 64 + nt * 8 + tig * 2;
        float b0v = bb[c], b1v = bb[c + 1];
        float s0 = 0.f, s1 = 0.f, q0 = 0.f, q1 = 0.f;
#pragma unroll
        for (int mt = 0; mt < 2; mt++) {
            int r0 = m0 + wm * 32 + mt * 16 + gid;
            int r1 = r0 + 8;
            float v0 = acc[mt][nt][0] + b0v;
            float v1 = acc[mt][nt][1] + b1v;
            float v2 = acc[mt][nt][2] + b0v;
            float v3 = acc[mt][nt][3] + b1v;
            if (r0 < M) {
                *(float2*)&out[(size_t)r0 * DD + c] = make_float2(v0, v1);
                s0 += v0; s1 += v1; q0 += v0 * v0; q1 += v1 * v1;
            }
            if (r1 < M) {
                *(float2*)&out[(size_t)r1 * DD + c] = make_float2(v2, v3);
                s0 += v2; s1 += v3; q0 += v2 * v2; q1 += v3 * v3;
            }
        }
        RED_GID(s0); RED_GID(s1); RED_GID(q0); RED_GID(q1);
        if (gid == 0) {
            atomicAdd(&cs[c], s0);
            atomicAdd(&cs[c + 1], s1);
            atomicAdd(&cq[c], q0);
            atomicAdd(&cq[c + 1], q1);
        }
    }
    __syncthreads();
    if (tid < 128) {
        atomicAdd(&csum[tid], (double)cs[tid]);
        atomicAdd(&csq[tid], (double)cq[tid]);
    }
}

// ---------------- BN stats -> scale/shift ----------------
__global__ void bnstat_k(const double* __restrict__ sum, const double* __restrict__ sq,
                         const float* __restrict__ gm, const float* __restrict__ bt,
                         float* __restrict__ sc, float* __restrict__ sh) {
    int d = threadIdx.x;
    double m = sum[d] / (double)NN;
    double v = sq[d] / (double)NN - m * m;
    float s = gm[d] * rsqrtf((float)v + 1e-5f);
    sc[d] = s;
    sh[d] = bt[d] - (float)m * s;
}

// ---------------- final BN apply (no relu) to d_out ----------------
__global__ void apply_k(const float* __restrict__ H, const float* __restrict__ sc,
                        const float* __restrict__ sh, float* __restrict__ out) {
    int i = blockIdx.x * blockDim.x + threadIdx.x;
    int total = NN * DD / 4;
    if (i < total) {
        float4 h = ((const float4*)H)[i];
        int d = (i * 4) & (DD - 1);
        float4 o;
        o.x = h.x * sc[d + 0] + sh[d + 0];
        o.y = h.y * sc[d + 1] + sh[d + 1];
        o.z = h.z * sc[d + 2] + sh[d + 2];
        o.w = h.w * sc[d + 3] + sh[d + 3];
        ((float4*)out)[i] = o;
    }
}

// ---------------- launch ----------------
extern "C" void kernel_launch(void* const* d_in, const int* in_sizes, int n_in,
                              void* d_out, int out_size) {
    const float* x   = (const float*)d_in[0];
    const int*   ei  = (const int*)d_in[1];     // int32
    const float* ea  = (const float*)d_in[2];
    const float* W1  = (const float*)d_in[4];
    const float* b1  = (const float*)d_in[5];
    const float* gmm = (const float*)d_in[6];
    const float* bmm = (const float*)d_in[7];
    const float* W2  = (const float*)d_in[8];
    const float* b2  = (const float*)d_in[9];
    const float* go  = (const float*)d_in[10];
    const float* bo  = (const float*)d_in[11];
    float*       out = (float*)d_out;

    const int* src = ei;
    const int* dst = ei + EE;

    int *deg, *off, *cur, *eid;
    float *Hagg, *H1, *H2, *sc1, *sh1, *scA, *shA;
    double* bn;
    cudaGetSymbolAddress((void**)&deg, g_deg);
    cudaGetSymbolAddress((void**)&off, g_off);
    cudaGetSymbolAddress((void**)&cur, g_cur);
    cudaGetSymbolAddress((void**)&eid, g_eid);
    cudaGetSymbolAddress((void**)&Hagg, g_Hagg);
    cudaGetSymbolAddress((void**)&H1, g_H1);
    cudaGetSymbolAddress((void**)&H2, g_H2);
    cudaGetSymbolAddress((void**)&bn, g_bn);
    cudaGetSymbolAddress((void**)&sc1, g_sc1);
    cudaGetSymbolAddress((void**)&sh1, g_sh1);
    cudaGetSymbolAddress((void**)&scA, g_scA);
    cudaGetSymbolAddress((void**)&shA, g_shA);

    // CSR build (once per launch, reused by all 3 layers)
    cudaMemsetAsync(deg, 0, NN * sizeof(int), 0);
    hist_k<<<1024, 256>>>(dst, deg);
    scan_k<<<1, 1024>>>(deg, off);
    cudaMemcpyAsync(cur, off, NN * sizeof(int), cudaMemcpyDeviceToDevice, 0);
    scat_k<<<1024, 256>>>(dst, cur, eid);
    init_sc_k<<<1, 128>>>(scA, shA);

    int MB = (NN + 127) / 128;
    int AGG_BLOCKS = (NN * 32 + 255) / 256;   // warp per node, 8 nodes/block
    for (int i = 0; i < LL; i++) {
        cudaMemsetAsync(bn, 0, 4 * DD * sizeof(double), 0);
        const float* Xin = (i == 0) ? x : H2;
        agg_k<<<AGG_BLOCKS, 256>>>(Xin, scA, shA, (i > 0) ? 1 : 0, src, ea, off, eid, Hagg);
        gemm_tc<0><<<MB, 256>>>(Hagg, W1 + (size_t)i * DD * DD, b1 + i * DD,
                                nullptr, nullptr, H1, bn, bn + DD, NN);
        bnstat_k<<<1, 128>>>(bn, bn + DD, gmm + i * DD, bmm + i * DD, sc1, sh1);
        gemm_tc<1><<<MB, 256>>>(H1, W2 + (size_t)i * DD * DD, b2 + i * DD,
                                sc1, sh1, H2, bn + 2 * DD, bn + 3 * DD, NN);
        bnstat_k<<<1, 128>>>(bn + 2 * DD, bn + 3 * DD, go + i * DD, bo + i * DD, scA, shA);
    }
    apply_k<<<(NN * DD / 4 + 255) / 256, 256>>>(H2, scA, shA, out);
}

// round 7
// speedup vs baseline: 1.1797x; 1.0643x over previous
#include <cuda_runtime.h>
#include <cstdint>

#define NN 50000
#define EE 800000
#define DD 128
#define LL 3

// ---------------- scratch (device globals: no allocation allowed) ----------------
__device__ int    g_deg[NN];
__device__ int    g_off[NN + 1];
__device__ int    g_cur[NN];
__device__ int    g_eid[EE];
__device__ __align__(16) float  g_Hagg[(size_t)NN * DD];
__device__ __align__(16) float  g_H1[(size_t)NN * DD];
__device__ __align__(16) float  g_H2[(size_t)NN * DD];
__device__ double g_bn[12 * DD];          // per layer: sum1, sq1, sum2, sq2
__device__ __align__(16) float  g_sc1[DD];
__device__ __align__(16) float  g_sh1[DD];
__device__ __align__(16) float  g_scA[DD];
__device__ __align__(16) float  g_shA[DD];
__device__ __align__(16) float  g_WH[6 * DD * DD];   // pre-split tf32 hi (W1[0..2], W2[0..2])
__device__ __align__(16) float  g_WL[6 * DD * DD];   // pre-split tf32 lo

// ---------------- tf32 helpers ----------------
__device__ __forceinline__ void tf32split(float a, float& hi, float& lo) {
    uint32_t u;
    asm("cvt.rna.tf32.f32 %0, %1;" : "=r"(u) : "f"(a));
    float h = __uint_as_float(u);
    float d = a - h;
    uint32_t ul;
    asm("cvt.rna.tf32.f32 %0, %1;" : "=r"(ul) : "f"(d));
    hi = h;
    lo = __uint_as_float(ul);
}

#define MMA_TF32(d, a, b)                                                     \
    asm volatile(                                                             \
        "mma.sync.aligned.m16n8k8.row.col.f32.tf32.tf32.f32 "                 \
        "{%0,%1,%2,%3},{%4,%5,%6,%7},{%8,%9},{%0,%1,%2,%3};"                  \
        : "+f"((d)[0]), "+f"((d)[1]), "+f"((d)[2]), "+f"((d)[3])              \
        : "r"((a)[0]), "r"((a)[1]), "r"((a)[2]), "r"((a)[3]),                 \
          "r"((b)[0]), "r"((b)[1]))

#define RED_GID(v)                                    \
    v += __shfl_xor_sync(0xffffffffu, v, 4);          \
    v += __shfl_xor_sync(0xffffffffu, v, 8);          \
    v += __shfl_xor_sync(0xffffffffu, v, 16);

// ---------------- CSR build ----------------
__global__ void hist_k(const int* __restrict__ dst, int* __restrict__ deg) {
    int i = blockIdx.x * blockDim.x + threadIdx.x;
    int st = gridDim.x * blockDim.x;
    for (int e = i; e < EE; e += st) atomicAdd(&deg[dst[e]], 1);
}

// scan + cur init + identity scale init (folds 2 launches)
__global__ void scan_k(const int* __restrict__ deg, int* __restrict__ off,
                       int* __restrict__ cur, float* __restrict__ scA,
                       float* __restrict__ shA) {
    __shared__ int part[1024];
    int t = threadIdx.x;
    if (t < DD) { scA[t] = 1.0f; shA[t] = 0.0f; }
    const int CH = (NN + 1023) / 1024;
    int s = t * CH;
    int e = min(s + CH, NN);
    int acc = 0;
    for (int i = s; i < e; i++) acc += deg[i];
    part[t] = acc;
    __syncthreads();
    for (int d = 1; d < 1024; d <<= 1) {
        int v = (t >= d) ? part[t - d] : 0;
        __syncthreads();
        part[t] += v;
        __syncthreads();
    }
    int run = (t == 0) ? 0 : part[t - 1];
    for (int i = s; i < e; i++) { off[i] = run; cur[i] = run; run += deg[i]; }
    if (t == 1023) off[NN] = part[1023];
}

__global__ void scat_k(const int* __restrict__ dst, int* __restrict__ cur,
                       int* __restrict__ eid) {
    int i = blockIdx.x * blockDim.x + threadIdx.x;
    int st = gridDim.x * blockDim.x;
    for (int e = i; e < EE; e += st) {
        int p = atomicAdd(&cur[dst[e]], 1);
        eid[p] = e;
    }
}

// ---------------- pre-split weights into tf32 hi/lo ----------------
__global__ void wsplit_k(const float* __restrict__ W1, const float* __restrict__ W2,
                         float* __restrict__ WH, float* __restrict__ WL) {
    int i = blockIdx.x * blockDim.x + threadIdx.x;
    const int SZ = LL * DD * DD;
    if (i < SZ) {
        float h, l;
        tf32split(W1[i], h, l);
        WH[i] = h; WL[i] = l;
        tf32split(W2[i], h, l);
        WH[SZ + i] = h; WL[SZ + i] = l;
    }
}

// ---------------- aggregation: h = x_eff + sum_e relu(x_eff[src] + ea) ----------------
__global__ void __launch_bounds__(256) agg_k(
    const float* __restrict__ X, const float* __restrict__ sc,
    const float* __restrict__ sh, int relu_in,
    const int* __restrict__ src, const float* __restrict__ ea,
    const int* __restrict__ off, const int* __restrict__ eid,
    float* __restrict__ out) {
    int warp = (blockIdx.x * blockDim.x + threadIdx.x) >> 5;
    if (warp >= NN) return;
    int lane = threadIdx.x & 31;
    int d0 = lane * 4;
    int row = warp;

    float4 s4 = *(const float4*)&sc[d0];
    float4 b4 = *(const float4*)&sh[d0];

    float4 v = *(const float4*)&X[(size_t)row * DD + d0];
    float4 acc;
    acc.x = v.x * s4.x + b4.x;
    acc.y = v.y * s4.y + b4.y;
    acc.z = v.z * s4.z + b4.z;
    acc.w = v.w * s4.w + b4.w;
    if (relu_in) {
        acc.x = fmaxf(acc.x, 0.0f); acc.y = fmaxf(acc.y, 0.0f);
        acc.z = fmaxf(acc.z, 0.0f); acc.w = fmaxf(acc.w, 0.0f);
    }

    int i0 = off[row], i1 = off[row + 1];
    int i = i0;
    for (; i + 1 < i1; i += 2) {
        int ea0 = eid[i], ea1 = eid[i + 1];
        int s0 = src[ea0], s1 = src[ea1];
        float4 x0 = *(const float4*)&X[(size_t)s0 * DD + d0];
        float4 x1 = *(const float4*)&X[(size_t)s1 * DD + d0];
        float4 e0 = *(const float4*)&ea[(size_t)ea0 * DD + d0];
        float4 e1 = *(const float4*)&ea[(size_t)ea1 * DD + d0];
        float4 t0, t1;
        t0.x = x0.x * s4.x + b4.x; t0.y = x0.y * s4.y + b4.y;
        t0.z = x0.z * s4.z + b4.z; t0.w = x0.w * s4.w + b4.w;
        t1.x = x1.x * s4.x + b4.x; t1.y = x1.y * s4.y + b4.y;
        t1.z = x1.z * s4.z + b4.z; t1.w = x1.w * s4.w + b4.w;
        if (relu_in) {
            t0.x = fmaxf(t0.x, 0.f); t0.y = fmaxf(t0.y, 0.f);
            t0.z = fmaxf(t0.z, 0.f); t0.w = fmaxf(t0.w, 0.f);
            t1.x = fmaxf(t1.x, 0.f); t1.y = fmaxf(t1.y, 0.f);
            t1.z = fmaxf(t1.z, 0.f); t1.w = fmaxf(t1.w, 0.f);
        }
        acc.x += fmaxf(t0.x + e0.x, 0.f) + fmaxf(t1.x + e1.x, 0.f);
        acc.y += fmaxf(t0.y + e0.y, 0.f) + fmaxf(t1.y + e1.y, 0.f);
        acc.z += fmaxf(t0.z + e0.z, 0.f) + fmaxf(t1.z + e1.z, 0.f);
        acc.w += fmaxf(t0.w + e0.w, 0.f) + fmaxf(t1.w + e1.w, 0.f);
    }
    if (i < i1) {
        int e0i = eid[i];
        int s0 = src[e0i];
        float4 x0 = *(const float4*)&X[(size_t)s0 * DD + d0];
        float4 e0 = *(const float4*)&ea[(size_t)e0i * DD + d0];
        float4 t0;
        t0.x = x0.x * s4.x + b4.x; t0.y = x0.y * s4.y + b4.y;
        t0.z = x0.z * s4.z + b4.z; t0.w = x0.w * s4.w + b4.w;
        if (relu_in) {
            t0.x = fmaxf(t0.x, 0.f); t0.y = fmaxf(t0.y, 0.f);
            t0.z = fmaxf(t0.z, 0.f); t0.w = fmaxf(t0.w, 0.f);
        }
        acc.x += fmaxf(t0.x + e0.x, 0.f);
        acc.y += fmaxf(t0.y + e0.y, 0.f);
        acc.z += fmaxf(t0.z + e0.z, 0.f);
        acc.w += fmaxf(t0.w + e0.w, 0.f);
    }
    *(float4*)&out[(size_t)row * DD + d0] = acc;
}

// ---------------- tensor-core GEMM v2 (3xTF32, resident B, pipelined A) ----------------
#define ASTR 20    // A smem stride (words): conflict-free for frag reads
#define BSTR 136   // B smem stride (words): conflict-free for frag reads
#define ABUF (128 * ASTR)
// dyn smem: BsH[128*BSTR] BsL[128*BSTR] AsH[2*ABUF] AsL[2*ABUF] bb fsc fsh cs cq (128 ea)
#define GEMM_SMEM ((2 * 128 * BSTR + 4 * ABUF + 5 * 128) * 4)

template <int FUSE>
__global__ void __launch_bounds__(256) gemm_tc(
    const float* __restrict__ A, const float* __restrict__ WH,
    const float* __restrict__ WL,
    const float* __restrict__ bias, const float* __restrict__ insc,
    const float* __restrict__ insh, float* __restrict__ out,
    double* __restrict__ csum, double* __restrict__ csq, int M) {
    extern __shared__ float smem[];
    float* BsH = smem;
    float* BsL = BsH + 128 * BSTR;
    float* AsH = BsL + 128 * BSTR;
    float* AsL = AsH + 2 * ABUF;
    float* bb  = AsL + 2 * ABUF;
    float* fsc = bb + 128;
    float* fsh = fsc + 128;
    float* cs  = fsh + 128;
    float* cq  = cs + 128;

    int tid = threadIdx.x;
    int lane = tid & 31, wid = tid >> 5;
    int wm = wid >> 1, wn = wid & 1;
    int gid = lane >> 2, tig = lane & 3;
    int m0 = blockIdx.x * 128;

    if (tid < 128) {
        bb[tid] = bias[tid];
        cs[tid] = 0.0f;
        cq[tid] = 0.0f;
        if (FUSE) { fsc[tid] = insc[tid]; fsh[tid] = insh[tid]; }
    }

    // load full pre-split B (128x128 hi+lo) once
#pragma unroll
    for (int i = tid; i < 128 * 32; i += 256) {
        int k = i >> 5;
        int n4 = (i & 31) << 2;
        *(float4*)&BsH[k * BSTR + n4] = *(const float4*)&WH[k * DD + n4];
        *(float4*)&BsL[k * BSTR + n4] = *(const float4*)&WL[k * DD + n4];
    }

    // A-chunk prefetch registers (128x16 per chunk = 2 float4 / thread)
    int ar = tid >> 1;                  // row 0..127
    int ac = (tid & 1) << 3;            // k offset 0 or 8
    float4 pa0, pa1;
    {
        float4 z = make_float4(0.f, 0.f, 0.f, 0.f);
        pa0 = z; pa1 = z;
        if (m0 + ar < M) {
            pa0 = *(const float4*)&A[(size_t)(m0 + ar) * DD + ac];
            pa1 = *(const float4*)&A[(size_t)(m0 + ar) * DD + ac + 4];
        }
    }

    float accm[2][8][4];
#pragma unroll
    for (int mt = 0; mt < 2; mt++)
#pragma unroll
        for (int nt = 0; nt < 8; nt++)
#pragma unroll
            for (int r = 0; r < 4; r++) accm[mt][nt][r] = 0.0f;

    // store chunk 0 into buf0
    {
        float vv[8] = {pa0.x, pa0.y, pa0.z, pa0.w, pa1.x, pa1.y, pa1.z, pa1.w};
        float* dh = &AsH[ar * ASTR + ac];
        float* dl = &AsL[ar * ASTR + ac];
#pragma unroll
        for (int j = 0; j < 8; j++) {
            float a = vv[j];
            if (FUSE) a = fmaxf(a * fsc[ac + j] + fsh[ac + j], 0.0f);
            float h, l;
            tf32split(a, h, l);
            dh[j] = h;
            dl[j] = l;
        }
    }
    __syncthreads();

    for (int ch = 0; ch < 8; ch++) {
        int kc = ch * 16;
        // issue next chunk's global loads early (latency hidden by MMAs)
        if (ch < 7) {
            float4 z = make_float4(0.f, 0.f, 0.f, 0.f);
            pa0 = z; pa1 = z;
            if (m0 + ar < M) {
                pa0 = *(const float4*)&A[(size_t)(m0 + ar) * DD + kc + 16 + ac];
                pa1 = *(const float4*)&A[(size_t)(m0 + ar) * DD + kc + 16 + ac + 4];
            }
        }
        const float* AH = &AsH[(ch & 1) * ABUF];
        const float* AL = &AsL[(ch & 1) * ABUF];
#pragma unroll
        for (int ks = 0; ks < 2; ks++) {
            int kl = ks * 8;           // k within chunk
            int kg = kc + kl;          // k within B
            uint32_t aH[2][4], aL[2][4], bH[8][2], bL[8][2];
#pragma unroll
            for (int mt = 0; mt < 2; mt++) {
                int r0 = wm * 32 + mt * 16 + gid;
                aH[mt][0] = __float_as_uint(AH[r0 * ASTR + kl + tig]);
                aH[mt][1] = __float_as_uint(AH[(r0 + 8) * ASTR + kl + tig]);
                aH[mt][2] = __float_as_uint(AH[r0 * ASTR + kl + tig + 4]);
                aH[mt][3] = __float_as_uint(AH[(r0 + 8) * ASTR + kl + tig + 4]);
                aL[mt][0] = __float_as_uint(AL[r0 * ASTR + kl + tig]);
                aL[mt][1] = __float_as_uint(AL[(r0 + 8) * ASTR + kl + tig]);
                aL[mt][2] = __float_as_uint(AL[r0 * ASTR + kl + tig + 4]);
                aL[mt][3] = __float_as_uint(AL[(r0 + 8) * ASTR + kl + tig + 4]);
            }
#pragma unroll
            for (int nt = 0; nt < 8; nt++) {
                int c = wn * 64 + nt * 8 + gid;
                bH[nt][0] = __float_as_uint(BsH[(kg + tig) * BSTR + c]);
                bH[nt][1] = __float_as_uint(BsH[(kg + tig + 4) * BSTR + c]);
                bL[nt][0] = __float_as_uint(BsL[(kg + tig) * BSTR + c]);
                bL[nt][1] = __float_as_uint(BsL[(kg + tig + 4) * BSTR + c]);
            }
#pragma unroll
            for (int mt = 0; mt < 2; mt++)
#pragma unroll
                for (int nt = 0; nt < 8; nt++) {
                    MMA_TF32(accm[mt][nt], aH[mt], bH[nt]);
                    MMA_TF32(accm[mt][nt], aH[mt], bL[nt]);
                    MMA_TF32(accm[mt][nt], aL[mt], bH[nt]);
                }
        }
        // split+store next chunk into the other buffer
        if (ch < 7) {
            int kn = kc + 16;
            float vv[8] = {pa0.x, pa0.y, pa0.z, pa0.w, pa1.x, pa1.y, pa1.z, pa1.w};
            float* dh = &AsH[((ch + 1) & 1) * ABUF + ar * ASTR + ac];
            float* dl = &AsL[((ch + 1) & 1) * ABUF + ar * ASTR + ac];
#pragma unroll
            for (int j = 0; j < 8; j++) {
                float a = vv[j];
                if (FUSE) a = fmaxf(a * fsc[kn + ac + j] + fsh[kn + ac + j], 0.0f);
                float h, l;
                tf32split(a, h, l);
                dh[j] = h;
                dl[j] = l;
            }
        }
        __syncthreads();
    }

    // epilogue: bias add, store, fused column sums (shfl-reduced over gid)
#pragma unroll
    for (int nt = 0; nt < 8; nt++) {
        int c = wn * 64 + nt * 8 + tig * 2;
        float b0v = bb[c], b1v = bb[c + 1];
        float s0 = 0.f, s1 = 0.f, q0 = 0.f, q1 = 0.f;
#pragma unroll
        for (int mt = 0; mt < 2; mt++) {
            int r0 = m0 + wm * 32 + mt * 16 + gid;
            int r1 = r0 + 8;
            float v0 = accm[mt][nt][0] + b0v;
            float v1 = accm[mt][nt][1] + b1v;
            float v2 = accm[mt][nt][2] + b0v;
            float v3 = accm[mt][nt][3] + b1v;
            if (r0 < M) {
                *(float2*)&out[(size_t)r0 * DD + c] = make_float2(v0, v1);
                s0 += v0; s1 += v1; q0 += v0 * v0; q1 += v1 * v1;
            }
            if (r1 < M) {
                *(float2*)&out[(size_t)r1 * DD + c] = make_float2(v2, v3);
                s0 += v2; s1 += v3; q0 += v2 * v2; q1 += v3 * v3;
            }
        }
        RED_GID(s0); RED_GID(s1); RED_GID(q0); RED_GID(q1);
        if (gid == 0) {
            atomicAdd(&cs[c], s0);
            atomicAdd(&cs[c + 1], s1);
            atomicAdd(&cq[c], q0);
            atomicAdd(&cq[c + 1], q1);
        }
    }
    __syncthreads();
    if (tid < 128) {
        atomicAdd(&csum[tid], (double)cs[tid]);
        atomicAdd(&csq[tid], (double)cq[tid]);
    }
}

// ---------------- BN stats -> scale/shift ----------------
__global__ void bnstat_k(const double* __restrict__ sum, const double* __restrict__ sq,
                         const float* __restrict__ gm, const float* __restrict__ bt,
                         float* __restrict__ sc, float* __restrict__ sh) {
    int d = threadIdx.x;
    double m = sum[d] / (double)NN;
    double v = sq[d] / (double)NN - m * m;
    float s = gm[d] * rsqrtf((float)v + 1e-5f);
    sc[d] = s;
    sh[d] = bt[d] - (float)m * s;
}

// ---------------- final BN apply (no relu) to d_out ----------------
__global__ void apply_k(const float* __restrict__ H, const float* __restrict__ sc,
                        const float* __restrict__ sh, float* __restrict__ out) {
    int i = blockIdx.x * blockDim.x + threadIdx.x;
    int total = NN * DD / 4;
    if (i < total) {
        float4 h = ((const float4*)H)[i];
        int d = (i * 4) & (DD - 1);
        float4 o;
        o.x = h.x * sc[d + 0] + sh[d + 0];
        o.y = h.y * sc[d + 1] + sh[d + 1];
        o.z = h.z * sc[d + 2] + sh[d + 2];
        o.w = h.w * sc[d + 3] + sh[d + 3];
        ((float4*)out)[i] = o;
    }
}

// ---------------- launch ----------------
extern "C" void kernel_launch(void* const* d_in, const int* in_sizes, int n_in,
                              void* d_out, int out_size) {
    const float* x   = (const float*)d_in[0];
    const int*   ei  = (const int*)d_in[1];     // int32
    const float* ea  = (const float*)d_in[2];
    const float* W1  = (const float*)d_in[4];
    const float* b1  = (const float*)d_in[5];
    const float* gmm = (const float*)d_in[6];
    const float* bmm = (const float*)d_in[7];
    const float* W2  = (const float*)d_in[8];
    const float* b2  = (const float*)d_in[9];
    const float* go  = (const float*)d_in[10];
    const float* bo  = (const float*)d_in[11];
    float*       out = (float*)d_out;

    const int* src = ei;
    const int* dst = ei + EE;

    int *deg, *off, *cur, *eid;
    float *Hagg, *H1, *H2, *sc1, *sh1, *scA, *shA, *WH, *WL;
    double* bn;
    cudaGetSymbolAddress((void**)&deg, g_deg);
    cudaGetSymbolAddress((void**)&off, g_off);
    cudaGetSymbolAddress((void**)&cur, g_cur);
    cudaGetSymbolAddress((void**)&eid, g_eid);
    cudaGetSymbolAddress((void**)&Hagg, g_Hagg);
    cudaGetSymbolAddress((void**)&H1, g_H1);
    cudaGetSymbolAddress((void**)&H2, g_H2);
    cudaGetSymbolAddress((void**)&bn, g_bn);
    cudaGetSymbolAddress((void**)&sc1, g_sc1);
    cudaGetSymbolAddress((void**)&sh1, g_sh1);
    cudaGetSymbolAddress((void**)&scA, g_scA);
    cudaGetSymbolAddress((void**)&shA, g_shA);
    cudaGetSymbolAddress((void**)&WH, g_WH);
    cudaGetSymbolAddress((void**)&WL, g_WL);

    static int attr_done = 0;
    if (!attr_done) {
        cudaFuncSetAttribute(gemm_tc<0>, cudaFuncAttributeMaxDynamicSharedMemorySize, GEMM_SMEM);
        cudaFuncSetAttribute(gemm_tc<1>, cudaFuncAttributeMaxDynamicSharedMemorySize, GEMM_SMEM);
        attr_done = 1;
    }

    // launch order: memset, memset, hist, scan, scat  (5 skipped) -> 6th = agg_k profiled
    cudaMemsetAsync(deg, 0, NN * sizeof(int), 0);
    cudaMemsetAsync(bn, 0, 12 * DD * sizeof(double), 0);
    hist_k<<<1024, 256>>>(dst, deg);
    scan_k<<<1, 1024>>>(deg, off, cur, scA, shA);
    scat_k<<<1024, 256>>>(dst, cur, eid);

    int MB = (NN + 127) / 128;
    int AGG_BLOCKS = (NN * 32 + 255) / 256;
    const int WSZ = LL * DD * DD;
    for (int i = 0; i < LL; i++) {
        const float* Xin = (i == 0) ? x : H2;
        double* bni = bn + (size_t)i * 4 * DD;
        agg_k<<<AGG_BLOCKS, 256>>>(Xin, scA, shA, (i > 0) ? 1 : 0, src, ea, off, eid, Hagg);
        if (i == 0)
            wsplit_k<<<(WSZ + 255) / 256, 256>>>(W1, W2, WH, WL);
        gemm_tc<0><<<MB, 256, GEMM_SMEM>>>(Hagg, WH + (size_t)i * DD * DD,
                                           WL + (size_t)i * DD * DD, b1 + i * DD,
                                           nullptr, nullptr, H1, bni, bni + DD, NN);
        bnstat_k<<<1, 128>>>(bni, bni + DD, gmm + i * DD, bmm + i * DD, sc1, sh1);
        gemm_tc<1><<<MB, 256, GEMM_SMEM>>>(H1, WH + (size_t)(WSZ + i * DD * DD),
                                           WL + (size_t)(WSZ + i * DD * DD), b2 + i * DD,
                                           sc1, sh1, H2, bni + 2 * DD, bni + 3 * DD, NN);
        bnstat_k<<<1, 128>>>(bni + 2 * DD, bni + 3 * DD, go + i * DD, bo + i * DD, scA, shA);
    }
    apply_k<<<(NN * DD / 4 + 255) / 256, 256>>>(H2, scA, shA, out);
}